// round 6
// baseline (speedup 1.0000x reference)
#include <cuda_runtime.h>
#include <math.h>
#include <stdint.h>

#define B_ 32768
#define M_ 10
#define BM_ (B_*M_)

// Scratch (allocation-free rule: __device__ globals)
__device__ float g_curx[(size_t)B_ * 1024];    // [z_top | r_top | h_top | q] per batch
__device__ float g_z     [(size_t)BM_ * 256];
__device__ float g_rp    [(size_t)BM_ * 256];
__device__ float g_scores[(size_t)B_ * 80];    // [b][head(8)][m(10)]
__device__ float g_x     [(size_t)B_ * 512];   // [cur | weighted_memory]
__device__ float g_f     [(size_t)B_ * 256];   // pre-LayerNorm fused

__device__ __forceinline__ float sigmoidf_(float x) { return 1.f / (1.f + expf(-x)); }

__device__ __forceinline__ uint32_t smem_u32(const void* p) {
    return (uint32_t)__cvta_generic_to_shared(p);
}
__device__ __forceinline__ void cp_async16(uint32_t s, const void* g) {
    asm volatile("cp.async.cg.shared.global [%0], [%1], 16;\n" :: "r"(s), "l"(g));
}
__device__ __forceinline__ void cp_commit() {
    asm volatile("cp.async.commit_group;\n");
}
template<int N>
__device__ __forceinline__ void cp_wait() {
    asm volatile("cp.async.wait_group %0;\n" :: "n"(N));
}

__device__ __forceinline__ void mma_tf32(float c[4], const uint32_t a[4], const uint32_t b[2]) {
    asm volatile(
        "mma.sync.aligned.m16n8k8.row.col.f32.tf32.tf32.f32 "
        "{%0,%1,%2,%3}, {%4,%5,%6,%7}, {%8,%9}, {%0,%1,%2,%3};"
        : "+f"(c[0]), "+f"(c[1]), "+f"(c[2]), "+f"(c[3])
        : "r"(a[0]), "r"(a[1]), "r"(a[2]), "r"(a[3]), "r"(b[0]), "r"(b[1]));
}

// ---------------------------------------------------------------------------
// tf32 tensor-core GEMM, 128x128 CTA tile, 128 threads (4 warps, 2m x 2n),
// warp tile 64x64, cp.async double-buffered.
// MODE 0: curx = cur @ {Wz,Wr,Wh,Wq}(top) + bias           -> g_curx     (K=256)
// MODE 1: {z,r} = sigmoid(prev @ {Wz,Wr}(bottom) + curx)   -> g_z, g_rp  (K=256)
// MODE 2: cand  = tanh(g_rp @ Wh(bottom) + curx_h); GRU    -> out        (K=256)
// MODE 3: scores = (upd@Wk + bk) . q  (per-head dot)       -> g_scores   (K=256)
// MODE 4: f     = g_x @ Wo + bo                            -> g_f        (K=512)
// ---------------------------------------------------------------------------
#define AS_STRIDE 36
#define BS_STRIDE 136
#define AS_ELEMS (128 * AS_STRIDE)
#define BS_ELEMS (32 * BS_STRIDE)

template<int MODE>
__global__ __launch_bounds__(128, 2)
void mma_gemm(const float* __restrict__ A,
              const float* __restrict__ Wa, const float* __restrict__ Wb,
              const float* __restrict__ Wc, const float* __restrict__ Wd,
              const float* __restrict__ ba, const float* __restrict__ bb,
              const float* __restrict__ bc, const float* __restrict__ bd,
              const float* __restrict__ prev,
              float* __restrict__ out)
{
    __shared__ __align__(16) float As[2][AS_ELEMS];
    __shared__ __align__(16) float Bs[2][BS_ELEMS];

    constexpr int KCH = (MODE == 4) ? 16 : 8;     // 32-wide K chunks
    constexpr int LDA = (MODE == 4) ? 512 : 256;  // A leading dim

    const int tid  = threadIdx.x;
    const int lane = tid & 31;
    const int warp = tid >> 5;            // 0..3
    const int wm   = warp >> 1;           // 0..1
    const int wn   = warp & 1;            // 0..1
    const int q    = lane >> 2;           // 0..7
    const int t4   = lane & 3;            // 0..3

    const int n0  = blockIdx.x * 128;
    const int m0  = blockIdx.y * 128;
    const int seg = n0 >> 8;
    const int ncol = n0 & 255;

    const float* W    = (seg == 0) ? Wa : (seg == 1) ? Wb : (seg == 2) ? Wc : Wd;
    const float* bias = (seg == 0) ? ba : (seg == 1) ? bb : (seg == 2) ? bc : bd;
    const float* Ap   = (MODE == 2) ? g_rp : (MODE == 4) ? g_x : A;

    float acc[4][8][4];
    #pragma unroll
    for (int i = 0; i < 4; i++)
        #pragma unroll
        for (int j = 0; j < 8; j++)
            #pragma unroll
            for (int v = 0; v < 4; v++) acc[i][j][v] = 0.f;

    auto load_chunk = [&](int bi, int k0) {
        #pragma unroll
        for (int i = 0; i < 8; i++) {
            int g = i * 128 + tid;              // 1024 A granules
            int m = g >> 3, c4 = (g & 7) << 2;
            cp_async16(smem_u32(&As[bi][m * AS_STRIDE + c4]),
                       Ap + (size_t)(m0 + m) * LDA + k0 + c4);
        }
        #pragma unroll
        for (int i = 0; i < 8; i++) {
            int g = i * 128 + tid;              // 1024 B granules
            int k = g >> 5, n4 = (g & 31) << 2;
            cp_async16(smem_u32(&Bs[bi][k * BS_STRIDE + n4]),
                       W + (size_t)(k0 + k) * 256 + ncol + n4);
        }
        cp_commit();
    };

    load_chunk(0, 0);

    for (int c = 0; c < KCH; c++) {
        const int buf = c & 1;
        if (c < KCH - 1) load_chunk(buf ^ 1, (c + 1) * 32);
        if (c < KCH - 1) cp_wait<1>(); else cp_wait<0>();
        __syncthreads();

        const float* Asb = As[buf];
        const float* Bsb = Bs[buf];
        #pragma unroll
        for (int kk = 0; kk < 4; kk++) {
            uint32_t a[4][4], b[8][2];
            const int col = kk * 8 + t4;
            #pragma unroll
            for (int mt = 0; mt < 4; mt++) {
                const int r0 = wm * 64 + mt * 16 + q;
                a[mt][0] = __float_as_uint(Asb[r0 * AS_STRIDE + col]);
                a[mt][1] = __float_as_uint(Asb[(r0 + 8) * AS_STRIDE + col]);
                a[mt][2] = __float_as_uint(Asb[r0 * AS_STRIDE + col + 4]);
                a[mt][3] = __float_as_uint(Asb[(r0 + 8) * AS_STRIDE + col + 4]);
            }
            #pragma unroll
            for (int nt = 0; nt < 8; nt++) {
                const int nb = wn * 64 + nt * 8 + q;
                b[nt][0] = __float_as_uint(Bsb[col * BS_STRIDE + nb]);
                b[nt][1] = __float_as_uint(Bsb[(col + 4) * BS_STRIDE + nb]);
            }
            #pragma unroll
            for (int mt = 0; mt < 4; mt++)
                #pragma unroll
                for (int nt = 0; nt < 8; nt++)
                    mma_tf32(acc[mt][nt], a[mt], b[nt]);
        }
        __syncthreads();
    }

    // ---------------- epilogue ----------------
    if (MODE == 3) {
        // scores: per (row, head) dot of k-row (acc + bias) with q, reduce over t4.
        #pragma unroll
        for (int mt = 0; mt < 4; mt++) {
            #pragma unroll
            for (int half = 0; half < 2; half++) {
                const int row = m0 + wm * 64 + mt * 16 + q + half * 8;
                const int b = row / 10, m = row - b * 10;
                const float* qp = g_curx + (size_t)b * 1024 + 768;
                #pragma unroll
                for (int hh = 0; hh < 2; hh++) {
                    float s = 0.f;
                    #pragma unroll
                    for (int j = 0; j < 4; j++) {
                        const int nt = hh * 4 + j;
                        const int col = n0 + wn * 64 + nt * 8 + 2 * t4;
                        float2 bk2 = *(const float2*)(ba + col);
                        float2 qv  = *(const float2*)(qp + col);
                        s += (acc[mt][nt][half * 2 + 0] + bk2.x) * qv.x
                           + (acc[mt][nt][half * 2 + 1] + bk2.y) * qv.y;
                    }
                    s += __shfl_xor_sync(0xffffffffu, s, 1);
                    s += __shfl_xor_sync(0xffffffffu, s, 2);
                    if (t4 == 0) {
                        const int head = (n0 >> 5) + wn * 2 + hh;
                        g_scores[((size_t)b * 8 + head) * 10 + m] = s;
                    }
                }
            }
        }
        return;
    }

    #pragma unroll
    for (int mt = 0; mt < 4; mt++) {
        #pragma unroll
        for (int nt = 0; nt < 8; nt++) {
            const int hl = wn * 64 + nt * 8 + 2 * t4;
            const int h  = ncol + hl;
            #pragma unroll
            for (int half = 0; half < 2; half++) {
                const int row = m0 + wm * 64 + mt * 16 + q + half * 8;
                const float v0 = acc[mt][nt][half * 2 + 0];
                const float v1 = acc[mt][nt][half * 2 + 1];
                if (MODE == 0) {
                    float2 bb2 = *(const float2*)(bias + h);
                    float2 o = make_float2(v0 + bb2.x, v1 + bb2.y);
                    *(float2*)(g_curx + (size_t)row * 1024 + seg * 256 + h) = o;
                } else if (MODE == 1) {
                    const int b = row / 10;
                    if (seg == 0) {
                        float2 cx = *(const float2*)(g_curx + (size_t)b * 1024 + h);
                        float2 o = make_float2(sigmoidf_(v0 + cx.x), sigmoidf_(v1 + cx.y));
                        *(float2*)(g_z + (size_t)row * 256 + h) = o;
                    } else {
                        float2 cx = *(const float2*)(g_curx + (size_t)b * 1024 + 256 + h);
                        float2 pv = *(const float2*)(prev + (size_t)row * 256 + h);
                        float2 o = make_float2(sigmoidf_(v0 + cx.x) * pv.x,
                                               sigmoidf_(v1 + cx.y) * pv.y);
                        *(float2*)(g_rp + (size_t)row * 256 + h) = o;
                    }
                } else if (MODE == 2) {
                    const int b = row / 10;
                    float2 cx = *(const float2*)(g_curx + (size_t)b * 1024 + 512 + h);
                    float2 zz = *(const float2*)(g_z + (size_t)row * 256 + h);
                    float2 pv = *(const float2*)(prev + (size_t)row * 256 + h);
                    float c0 = tanhf(v0 + cx.x), c1 = tanhf(v1 + cx.y);
                    float2 o = make_float2((1.f - zz.x) * pv.x + zz.x * c0,
                                           (1.f - zz.y) * pv.y + zz.y * c1);
                    *(float2*)(out + (size_t)row * 256 + h) = o;
                } else {  // MODE 4: out projection -> g_f
                    float2 bb2 = *(const float2*)(bias + h);
                    float2 o = make_float2(v0 + bb2.x, v1 + bb2.y);
                    *(float2*)(g_f + (size_t)row * 256 + h) = o;
                }
            }
        }
    }
}

// ---------------------------------------------------------------------------
// attn_light: softmax + head-mean over g_scores, weighted memory, build x.
// GB=32 batches/CTA. Memory-bound.
// ---------------------------------------------------------------------------
#define GB_ 32

__global__ __launch_bounds__(256)
void attn_light(const float* __restrict__ cur,
                float* __restrict__ d_out)
{
    __shared__ float ss[GB_ * 80];
    __shared__ float sattn[GB_ * 10];

    const int tid = threadIdx.x;
    const int b0 = blockIdx.x * GB_;
    const float* upd = d_out + (size_t)B_ * 256;
    float* attn_out  = d_out + (size_t)B_ * 256 + (size_t)BM_ * 256;

    // load scores (apply 1/sqrt(32) here)
    const float scale = 0.17677669529663687f;
    for (int t = tid; t < GB_ * 80; t += 256)
        ss[t] = g_scores[(size_t)b0 * 80 + t] * scale;
    __syncthreads();

    // softmax over m per (bi, head)
    for (int t = tid; t < GB_ * 8; t += 256) {
        float* row = ss + t * 10;
        float mx = row[0];
        #pragma unroll
        for (int m = 1; m < 10; m++) mx = fmaxf(mx, row[m]);
        float e[10], sum = 0.f;
        #pragma unroll
        for (int m = 0; m < 10; m++) { e[m] = expf(row[m] - mx); sum += e[m]; }
        float inv = 1.f / sum;
        #pragma unroll
        for (int m = 0; m < 10; m++) row[m] = e[m] * inv;
    }
    __syncthreads();

    // head mean
    for (int t = tid; t < GB_ * 10; t += 256) {
        int bi = t / 10, m = t % 10;
        float s = 0.f;
        #pragma unroll
        for (int n = 0; n < 8; n++) s += ss[(bi * 8 + n) * 10 + m];
        s *= 0.125f;
        sattn[t] = s;
        attn_out[(size_t)(b0 + bi) * 10 + m] = s;
    }
    __syncthreads();

    // weighted memory; write x = [cur | weighted] to g_x
    for (int idx = tid; idx < GB_ * 256; idx += 256) {
        int bi = idx >> 8, h = idx & 255;
        size_t base = ((size_t)(b0 + bi) * 10) * 256 + h;
        float s = 0.f;
        #pragma unroll
        for (int m = 0; m < 10; m++) s += upd[base + m * 256] * sattn[bi * 10 + m];
        g_x[(size_t)(b0 + bi) * 512 + h]       = cur[(size_t)(b0 + bi) * 256 + h];
        g_x[(size_t)(b0 + bi) * 512 + 256 + h] = s;
    }
}

// ---------------------------------------------------------------------------
// LayerNorm over g_f -> d_out. One warp per row, 8 rows/CTA.
// ---------------------------------------------------------------------------
__global__ __launch_bounds__(256)
void ln_kernel(const float* __restrict__ gamma, const float* __restrict__ beta,
               float* __restrict__ d_out)
{
    const int warp = threadIdx.x >> 5;
    const int lane = threadIdx.x & 31;
    const int row  = blockIdx.x * 8 + warp;

    float v[8], sum = 0.f;
    const float* src = g_f + (size_t)row * 256;
    #pragma unroll
    for (int i = 0; i < 8; i++) { v[i] = src[lane + 32 * i]; sum += v[i]; }
    #pragma unroll
    for (int o = 16; o > 0; o >>= 1) sum += __shfl_xor_sync(0xffffffffu, sum, o);
    float mu = sum * (1.f / 256.f);
    float sq = 0.f;
    #pragma unroll
    for (int i = 0; i < 8; i++) { float d = v[i] - mu; sq += d * d; }
    #pragma unroll
    for (int o = 16; o > 0; o >>= 1) sq += __shfl_xor_sync(0xffffffffu, sq, o);
    float rstd = rsqrtf(sq * (1.f / 256.f) + 1e-5f);
    float* dst = d_out + (size_t)row * 256;
    #pragma unroll
    for (int i = 0; i < 8; i++) {
        int d_ = lane + 32 * i;
        dst[d_] = (v[i] - mu) * rstd * gamma[d_] + beta[d_];
    }
}

extern "C" void kernel_launch(void* const* d_in, const int* in_sizes, int n_in,
                              void* d_out, int out_size)
{
    (void)in_sizes; (void)n_in; (void)out_size;
    const float* cur    = (const float*)d_in[0];
    const float* prev   = (const float*)d_in[1];
    const float* Wz     = (const float*)d_in[2];
    const float* bz     = (const float*)d_in[3];
    const float* Wr     = (const float*)d_in[4];
    const float* br     = (const float*)d_in[5];
    const float* Wh     = (const float*)d_in[6];
    const float* bh     = (const float*)d_in[7];
    const float* Wq     = (const float*)d_in[8];
    const float* bq     = (const float*)d_in[9];
    const float* Wk     = (const float*)d_in[10];
    const float* bk     = (const float*)d_in[11];
    const float* Wo     = (const float*)d_in[12];
    const float* bo     = (const float*)d_in[13];
    const float* gamma2 = (const float*)d_in[14];
    const float* beta2  = (const float*)d_in[15];
    float* out = (float*)d_out;
    float* upd = out + (size_t)B_ * 256;

    dim3 blk(128);
    // 1) cur projections: [B,256] @ [256,1024]
    mma_gemm<0><<<dim3(8, B_ / 128), blk>>>(cur, Wz, Wr, Wh, Wq,
                                            bz, br, bh, bq, nullptr, nullptr);
    // 2) z/r gates: [BM,256] @ [256,512]
    mma_gemm<1><<<dim3(4, BM_ / 128), blk>>>(prev, Wz + 65536, Wr + 65536, nullptr, nullptr,
                                             nullptr, nullptr, nullptr, nullptr, prev, nullptr);
    // 3) cand + GRU update -> updated_memory
    mma_gemm<2><<<dim3(2, BM_ / 128), blk>>>(nullptr, Wh + 65536, nullptr, nullptr, nullptr,
                                             nullptr, nullptr, nullptr, nullptr, prev, upd);
    // 4) k projection + fused attention scores -> g_scores
    mma_gemm<3><<<dim3(2, BM_ / 128), blk>>>(upd, Wk, nullptr, nullptr, nullptr,
                                             bk, nullptr, nullptr, nullptr, nullptr, nullptr);
    // 5) softmax/head-mean/weighted -> g_x, attn weights
    attn_light<<<dim3(B_ / GB_), dim3(256)>>>(cur, out);
    // 6) output projection: [B,512] @ [512,256] -> g_f
    mma_gemm<4><<<dim3(2, B_ / 128), blk>>>(nullptr, Wo, nullptr, nullptr, nullptr,
                                            bo, nullptr, nullptr, nullptr, nullptr, nullptr);
    // 7) LayerNorm -> d_out
    ln_kernel<<<dim3(B_ / 8), dim3(256)>>>(gamma2, beta2, out);
}

// round 7
// speedup vs baseline: 1.2999x; 1.2999x over previous
#include <cuda_runtime.h>
#include <math.h>
#include <stdint.h>

#define B_ 32768
#define M_ 10
#define BM_ (B_*M_)

// Scratch (allocation-free rule: __device__ globals)
__device__ float g_curx[(size_t)B_ * 1024];    // [z_top | r_top | h_top | q] per batch
__device__ float g_z     [(size_t)BM_ * 256];
__device__ float g_rp    [(size_t)BM_ * 256];
__device__ float g_scores[(size_t)B_ * 80];    // [b][head(8)][m(10)]
__device__ float g_x     [(size_t)B_ * 512];   // [cur | weighted_memory]
__device__ float g_f     [(size_t)B_ * 256];   // pre-LayerNorm fused

__device__ __forceinline__ float sigmoidf_(float x) { return 1.f / (1.f + expf(-x)); }

__device__ __forceinline__ uint32_t smem_u32(const void* p) {
    return (uint32_t)__cvta_generic_to_shared(p);
}
__device__ __forceinline__ void cp_async16(uint32_t s, const void* g) {
    asm volatile("cp.async.cg.shared.global [%0], [%1], 16;\n" :: "r"(s), "l"(g));
}
__device__ __forceinline__ void cp_commit() {
    asm volatile("cp.async.commit_group;\n");
}
template<int N>
__device__ __forceinline__ void cp_wait() {
    asm volatile("cp.async.wait_group %0;\n" :: "n"(N));
}

__device__ __forceinline__ void mma_tf32(float c[4], const uint32_t a[4], const uint32_t b[2]) {
    asm volatile(
        "mma.sync.aligned.m16n8k8.row.col.f32.tf32.tf32.f32 "
        "{%0,%1,%2,%3}, {%4,%5,%6,%7}, {%8,%9}, {%0,%1,%2,%3};"
        : "+f"(c[0]), "+f"(c[1]), "+f"(c[2]), "+f"(c[3])
        : "r"(a[0]), "r"(a[1]), "r"(a[2]), "r"(a[3]), "r"(b[0]), "r"(b[1]));
}

// ---------------------------------------------------------------------------
// tf32 tensor-core GEMM, 128x128 CTA tile, 256 threads (8 warps, 2m x 4n),
// warp tile 64x32, cp.async double-buffered.  (round-5 proven engine)
// MODE 0: curx = cur @ {Wz,Wr,Wh,Wq}(top) + bias           -> g_curx     (K=256)
// MODE 1: {z,r} = sigmoid(prev @ {Wz,Wr}(bottom) + curx)   -> g_z, g_rp  (K=256)
// MODE 2: cand  = tanh(g_rp @ Wh(bottom) + curx_h); GRU    -> out        (K=256)
// MODE 3: scores = (upd@Wk + bk) . q  (per-head dot)       -> g_scores   (K=256)
// MODE 4: f     = g_x @ Wo + bo                            -> g_f        (K=512)
// ---------------------------------------------------------------------------
#define AS_STRIDE 36
#define BS_STRIDE 136
#define AS_ELEMS (128 * AS_STRIDE)
#define BS_ELEMS (32 * BS_STRIDE)

template<int MODE>
__global__ __launch_bounds__(256, 2)
void mma_gemm(const float* __restrict__ A,
              const float* __restrict__ Wa, const float* __restrict__ Wb,
              const float* __restrict__ Wc, const float* __restrict__ Wd,
              const float* __restrict__ ba, const float* __restrict__ bb,
              const float* __restrict__ bc, const float* __restrict__ bd,
              const float* __restrict__ prev,
              float* __restrict__ out)
{
    __shared__ __align__(16) float As[2][AS_ELEMS];
    __shared__ __align__(16) float Bs[2][BS_ELEMS];

    constexpr int KCH = (MODE == 4) ? 16 : 8;     // 32-wide K chunks
    constexpr int LDA = (MODE == 4) ? 512 : 256;  // A leading dim

    const int tid  = threadIdx.x;
    const int lane = tid & 31;
    const int warp = tid >> 5;
    const int wm   = warp >> 2;           // 0..1
    const int wn   = warp & 3;            // 0..3
    const int q    = lane >> 2;           // 0..7
    const int t4   = lane & 3;            // 0..3

    const int n0  = blockIdx.x * 128;
    const int m0  = blockIdx.y * 128;
    const int seg = n0 >> 8;
    const int ncol = n0 & 255;

    const float* W    = (seg == 0) ? Wa : (seg == 1) ? Wb : (seg == 2) ? Wc : Wd;
    const float* bias = (seg == 0) ? ba : (seg == 1) ? bb : (seg == 2) ? bc : bd;
    const float* Ap   = (MODE == 2) ? g_rp : (MODE == 4) ? g_x : A;

    float acc[4][4][4];
    #pragma unroll
    for (int i = 0; i < 4; i++)
        #pragma unroll
        for (int j = 0; j < 4; j++)
            #pragma unroll
            for (int v = 0; v < 4; v++) acc[i][j][v] = 0.f;

    auto load_chunk = [&](int bi, int k0) {
        #pragma unroll
        for (int i = 0; i < 4; i++) {
            int g = i * 256 + tid;
            int m = g >> 3, c4 = (g & 7) << 2;
            cp_async16(smem_u32(&As[bi][m * AS_STRIDE + c4]),
                       Ap + (size_t)(m0 + m) * LDA + k0 + c4);
        }
        #pragma unroll
        for (int i = 0; i < 4; i++) {
            int g = i * 256 + tid;
            int k = g >> 5, n4 = (g & 31) << 2;
            cp_async16(smem_u32(&Bs[bi][k * BS_STRIDE + n4]),
                       W + (size_t)(k0 + k) * 256 + ncol + n4);
        }
        cp_commit();
    };

    load_chunk(0, 0);

    for (int c = 0; c < KCH; c++) {
        const int buf = c & 1;
        if (c < KCH - 1) load_chunk(buf ^ 1, (c + 1) * 32);
        if (c < KCH - 1) cp_wait<1>(); else cp_wait<0>();
        __syncthreads();

        const float* Asb = As[buf];
        const float* Bsb = Bs[buf];
        #pragma unroll
        for (int kk = 0; kk < 4; kk++) {
            uint32_t a[4][4], b[4][2];
            const int col = kk * 8 + t4;
            #pragma unroll
            for (int mt = 0; mt < 4; mt++) {
                const int r0 = wm * 64 + mt * 16 + q;
                a[mt][0] = __float_as_uint(Asb[r0 * AS_STRIDE + col]);
                a[mt][1] = __float_as_uint(Asb[(r0 + 8) * AS_STRIDE + col]);
                a[mt][2] = __float_as_uint(Asb[r0 * AS_STRIDE + col + 4]);
                a[mt][3] = __float_as_uint(Asb[(r0 + 8) * AS_STRIDE + col + 4]);
            }
            #pragma unroll
            for (int nt = 0; nt < 4; nt++) {
                const int nb = wn * 32 + nt * 8 + q;
                b[nt][0] = __float_as_uint(Bsb[col * BS_STRIDE + nb]);
                b[nt][1] = __float_as_uint(Bsb[(col + 4) * BS_STRIDE + nb]);
            }
            #pragma unroll
            for (int mt = 0; mt < 4; mt++)
                #pragma unroll
                for (int nt = 0; nt < 4; nt++)
                    mma_tf32(acc[mt][nt], a[mt], b[nt]);
        }
        __syncthreads();
    }

    // ---------------- epilogue ----------------
    if (MODE == 3) {
        // Each warp covers 32 cols = exactly one head: head = n0/32 + wn.
        // score(row, head) = sum over 32 dims of (k + bk) * q, reduce over t4.
        const int head = (n0 >> 5) + wn;
        #pragma unroll
        for (int mt = 0; mt < 4; mt++) {
            #pragma unroll
            for (int half = 0; half < 2; half++) {
                const int row = m0 + wm * 64 + mt * 16 + q + half * 8;
                const int b = row / 10, m = row - b * 10;
                const float* qp = g_curx + (size_t)b * 1024 + 768;
                float s = 0.f;
                #pragma unroll
                for (int nt = 0; nt < 4; nt++) {
                    const int col = n0 + wn * 32 + nt * 8 + 2 * t4;
                    float2 bk2 = *(const float2*)(ba + col);
                    float2 qv  = *(const float2*)(qp + col);
                    s += (acc[mt][nt][half * 2 + 0] + bk2.x) * qv.x
                       + (acc[mt][nt][half * 2 + 1] + bk2.y) * qv.y;
                }
                s += __shfl_xor_sync(0xffffffffu, s, 1);
                s += __shfl_xor_sync(0xffffffffu, s, 2);
                if (t4 == 0)
                    g_scores[((size_t)b * 8 + head) * 10 + m] = s;
            }
        }
        return;
    }

    #pragma unroll
    for (int mt = 0; mt < 4; mt++) {
        #pragma unroll
        for (int nt = 0; nt < 4; nt++) {
            const int hl = wn * 32 + nt * 8 + 2 * t4;
            const int h  = ncol + hl;
            #pragma unroll
            for (int half = 0; half < 2; half++) {
                const int row = m0 + wm * 64 + mt * 16 + q + half * 8;
                const float v0 = acc[mt][nt][half * 2 + 0];
                const float v1 = acc[mt][nt][half * 2 + 1];
                if (MODE == 0) {
                    float2 bb2 = *(const float2*)(bias + h);
                    float2 o = make_float2(v0 + bb2.x, v1 + bb2.y);
                    *(float2*)(g_curx + (size_t)row * 1024 + seg * 256 + h) = o;
                } else if (MODE == 1) {
                    const int b = row / 10;
                    if (seg == 0) {
                        float2 cx = *(const float2*)(g_curx + (size_t)b * 1024 + h);
                        float2 o = make_float2(sigmoidf_(v0 + cx.x), sigmoidf_(v1 + cx.y));
                        *(float2*)(g_z + (size_t)row * 256 + h) = o;
                    } else {
                        float2 cx = *(const float2*)(g_curx + (size_t)b * 1024 + 256 + h);
                        float2 pv = *(const float2*)(prev + (size_t)row * 256 + h);
                        float2 o = make_float2(sigmoidf_(v0 + cx.x) * pv.x,
                                               sigmoidf_(v1 + cx.y) * pv.y);
                        *(float2*)(g_rp + (size_t)row * 256 + h) = o;
                    }
                } else if (MODE == 2) {
                    const int b = row / 10;
                    float2 cx = *(const float2*)(g_curx + (size_t)b * 1024 + 512 + h);
                    float2 zz = *(const float2*)(g_z + (size_t)row * 256 + h);
                    float2 pv = *(const float2*)(prev + (size_t)row * 256 + h);
                    float c0 = tanhf(v0 + cx.x), c1 = tanhf(v1 + cx.y);
                    float2 o = make_float2((1.f - zz.x) * pv.x + zz.x * c0,
                                           (1.f - zz.y) * pv.y + zz.y * c1);
                    *(float2*)(out + (size_t)row * 256 + h) = o;
                } else {  // MODE 4: out projection -> g_f
                    float2 bb2 = *(const float2*)(bias + h);
                    float2 o = make_float2(v0 + bb2.x, v1 + bb2.y);
                    *(float2*)(g_f + (size_t)row * 256 + h) = o;
                }
            }
        }
    }
}

// ---------------------------------------------------------------------------
// attn_light: softmax + head-mean over g_scores, weighted memory, build x.
// GB=32 batches/CTA. Memory-bound.
// ---------------------------------------------------------------------------
#define GB_ 32

__global__ __launch_bounds__(256)
void attn_light(const float* __restrict__ cur,
                float* __restrict__ d_out)
{
    __shared__ float ss[GB_ * 80];
    __shared__ float sattn[GB_ * 10];

    const int tid = threadIdx.x;
    const int b0 = blockIdx.x * GB_;
    const float* upd = d_out + (size_t)B_ * 256;
    float* attn_out  = d_out + (size_t)B_ * 256 + (size_t)BM_ * 256;

    // load scores (apply 1/sqrt(32) here)
    const float scale = 0.17677669529663687f;
    for (int t = tid; t < GB_ * 80; t += 256)
        ss[t] = g_scores[(size_t)b0 * 80 + t] * scale;
    __syncthreads();

    // softmax over m per (bi, head)
    for (int t = tid; t < GB_ * 8; t += 256) {
        float* row = ss + t * 10;
        float mx = row[0];
        #pragma unroll
        for (int m = 1; m < 10; m++) mx = fmaxf(mx, row[m]);
        float e[10], sum = 0.f;
        #pragma unroll
        for (int m = 0; m < 10; m++) { e[m] = expf(row[m] - mx); sum += e[m]; }
        float inv = 1.f / sum;
        #pragma unroll
        for (int m = 0; m < 10; m++) row[m] = e[m] * inv;
    }
    __syncthreads();

    // head mean
    for (int t = tid; t < GB_ * 10; t += 256) {
        int bi = t / 10, m = t % 10;
        float s = 0.f;
        #pragma unroll
        for (int n = 0; n < 8; n++) s += ss[(bi * 8 + n) * 10 + m];
        s *= 0.125f;
        sattn[t] = s;
        attn_out[(size_t)(b0 + bi) * 10 + m] = s;
    }
    __syncthreads();

    // weighted memory; write x = [cur | weighted] to g_x
    for (int idx = tid; idx < GB_ * 256; idx += 256) {
        int bi = idx >> 8, h = idx & 255;
        size_t base = ((size_t)(b0 + bi) * 10) * 256 + h;
        float s = 0.f;
        #pragma unroll
        for (int m = 0; m < 10; m++) s += upd[base + m * 256] * sattn[bi * 10 + m];
        g_x[(size_t)(b0 + bi) * 512 + h]       = cur[(size_t)(b0 + bi) * 256 + h];
        g_x[(size_t)(b0 + bi) * 512 + 256 + h] = s;
    }
}

// ---------------------------------------------------------------------------
// LayerNorm over g_f -> d_out. One warp per row, 8 rows/CTA.
// ---------------------------------------------------------------------------
__global__ __launch_bounds__(256)
void ln_kernel(const float* __restrict__ gamma, const float* __restrict__ beta,
               float* __restrict__ d_out)
{
    const int warp = threadIdx.x >> 5;
    const int lane = threadIdx.x & 31;
    const int row  = blockIdx.x * 8 + warp;

    float v[8], sum = 0.f;
    const float* src = g_f + (size_t)row * 256;
    #pragma unroll
    for (int i = 0; i < 8; i++) { v[i] = src[lane + 32 * i]; sum += v[i]; }
    #pragma unroll
    for (int o = 16; o > 0; o >>= 1) sum += __shfl_xor_sync(0xffffffffu, sum, o);
    float mu = sum * (1.f / 256.f);
    float sq = 0.f;
    #pragma unroll
    for (int i = 0; i < 8; i++) { float d = v[i] - mu; sq += d * d; }
    #pragma unroll
    for (int o = 16; o > 0; o >>= 1) sq += __shfl_xor_sync(0xffffffffu, sq, o);
    float rstd = rsqrtf(sq * (1.f / 256.f) + 1e-5f);
    float* dst = d_out + (size_t)row * 256;
    #pragma unroll
    for (int i = 0; i < 8; i++) {
        int d_ = lane + 32 * i;
        dst[d_] = (v[i] - mu) * rstd * gamma[d_] + beta[d_];
    }
}

extern "C" void kernel_launch(void* const* d_in, const int* in_sizes, int n_in,
                              void* d_out, int out_size)
{
    (void)in_sizes; (void)n_in; (void)out_size;
    const float* cur    = (const float*)d_in[0];
    const float* prev   = (const float*)d_in[1];
    const float* Wz     = (const float*)d_in[2];
    const float* bz     = (const float*)d_in[3];
    const float* Wr     = (const float*)d_in[4];
    const float* br     = (const float*)d_in[5];
    const float* Wh     = (const float*)d_in[6];
    const float* bh     = (const float*)d_in[7];
    const float* Wq     = (const float*)d_in[8];
    const float* bq     = (const float*)d_in[9];
    const float* Wk     = (const float*)d_in[10];
    const float* bk     = (const float*)d_in[11];
    const float* Wo     = (const float*)d_in[12];
    const float* bo     = (const float*)d_in[13];
    const float* gamma2 = (const float*)d_in[14];
    const float* beta2  = (const float*)d_in[15];
    float* out = (float*)d_out;
    float* upd = out + (size_t)B_ * 256;

    dim3 blk(256);
    // 1) cur projections: [B,256] @ [256,1024]
    mma_gemm<0><<<dim3(8, B_ / 128), blk>>>(cur, Wz, Wr, Wh, Wq,
                                            bz, br, bh, bq, nullptr, nullptr);
    // 2) z/r gates: [BM,256] @ [256,512]
    mma_gemm<1><<<dim3(4, BM_ / 128), blk>>>(prev, Wz + 65536, Wr + 65536, nullptr, nullptr,
                                             nullptr, nullptr, nullptr, nullptr, prev, nullptr);
    // 3) cand + GRU update -> updated_memory
    mma_gemm<2><<<dim3(2, BM_ / 128), blk>>>(nullptr, Wh + 65536, nullptr, nullptr, nullptr,
                                             nullptr, nullptr, nullptr, nullptr, prev, upd);
    // 4) k projection + fused attention scores -> g_scores
    mma_gemm<3><<<dim3(2, BM_ / 128), blk>>>(upd, Wk, nullptr, nullptr, nullptr,
                                             bk, nullptr, nullptr, nullptr, nullptr, nullptr);
    // 5) softmax/head-mean/weighted -> g_x, attn weights
    attn_light<<<dim3(B_ / GB_), dim3(256)>>>(cur, out);
    // 6) output projection: [B,512] @ [512,256] -> g_f
    mma_gemm<4><<<dim3(2, B_ / 128), blk>>>(nullptr, Wo, nullptr, nullptr, nullptr,
                                            bo, nullptr, nullptr, nullptr, nullptr, nullptr);
    // 7) LayerNorm -> d_out
    ln_kernel<<<dim3(B_ / 8), dim3(256)>>>(gamma2, beta2, out);
}

// round 8
// speedup vs baseline: 1.3188x; 1.0146x over previous
#include <cuda_runtime.h>
#include <math.h>
#include <stdint.h>

#define B_ 32768
#define M_ 10
#define BM_ (B_*M_)

// Scratch (allocation-free rule: __device__ globals)
__device__ float g_curx[(size_t)B_ * 1024];    // [z_top | r_top | h_top | q] per batch
__device__ float g_z     [(size_t)BM_ * 256];
__device__ float g_rp    [(size_t)BM_ * 256];
__device__ float g_scores[(size_t)B_ * 80];    // [b][head(8)][m(10)]
__device__ float g_x     [(size_t)B_ * 512];   // [cur | weighted_memory]
__device__ float g_f     [(size_t)B_ * 256];   // pre-LayerNorm fused

__device__ __forceinline__ float sigmoidf_(float x) { return 1.f / (1.f + expf(-x)); }

__device__ __forceinline__ uint32_t smem_u32(const void* p) {
    return (uint32_t)__cvta_generic_to_shared(p);
}
__device__ __forceinline__ void cp_async16(uint32_t s, const void* g) {
    asm volatile("cp.async.cg.shared.global [%0], [%1], 16;\n" :: "r"(s), "l"(g));
}
__device__ __forceinline__ void cp_commit() {
    asm volatile("cp.async.commit_group;\n");
}
template<int N>
__device__ __forceinline__ void cp_wait() {
    asm volatile("cp.async.wait_group %0;\n" :: "n"(N));
}

__device__ __forceinline__ void mma_tf32(float c[4], const uint32_t a[4], const uint32_t b[2]) {
    asm volatile(
        "mma.sync.aligned.m16n8k8.row.col.f32.tf32.tf32.f32 "
        "{%0,%1,%2,%3}, {%4,%5,%6,%7}, {%8,%9}, {%0,%1,%2,%3};"
        : "+f"(c[0]), "+f"(c[1]), "+f"(c[2]), "+f"(c[3])
        : "r"(a[0]), "r"(a[1]), "r"(a[2]), "r"(a[3]), "r"(b[0]), "r"(b[1]));
}

// ---------------------------------------------------------------------------
// tf32 tensor-core GEMM, 128x128 CTA tile, 256 threads (8 warps, 2m x 4n),
// warp tile 64x32. Triple-buffered cp.async pipeline, ONE barrier per chunk.
// MODE 0: curx = cur @ {Wz,Wr,Wh,Wq}(top) + bias           -> g_curx     (K=256)
// MODE 1: {z,r} = sigmoid(prev @ {Wz,Wr}(bottom) + curx)   -> g_z, g_rp  (K=256)
// MODE 2: cand  = tanh(g_rp @ Wh(bottom) + curx_h); GRU    -> out        (K=256)
// MODE 3: scores = (upd@Wk + bk) . q  (per-head dot)       -> g_scores   (K=256)
// MODE 4: f     = g_x @ Wo + bo                            -> g_f        (K=512)
// ---------------------------------------------------------------------------
#define AS_STRIDE 36
#define BS_STRIDE 136
#define AS_ELEMS (128 * AS_STRIDE)
#define BS_ELEMS (32 * BS_STRIDE)
#define BUF_ELEMS (AS_ELEMS + BS_ELEMS)
#define GEMM_SMEM (3 * BUF_ELEMS * sizeof(float))

template<int MODE>
__global__ __launch_bounds__(256, 2)
void mma_gemm(const float* __restrict__ A,
              const float* __restrict__ Wa, const float* __restrict__ Wb,
              const float* __restrict__ Wc, const float* __restrict__ Wd,
              const float* __restrict__ ba, const float* __restrict__ bb,
              const float* __restrict__ bc, const float* __restrict__ bd,
              const float* __restrict__ prev,
              float* __restrict__ out)
{
    extern __shared__ __align__(16) float sm3[];   // 3 x [As | Bs]

    constexpr int KCH = (MODE == 4) ? 16 : 8;     // 32-wide K chunks
    constexpr int LDA = (MODE == 4) ? 512 : 256;  // A leading dim

    const int tid  = threadIdx.x;
    const int lane = tid & 31;
    const int warp = tid >> 5;
    const int wm   = warp >> 2;           // 0..1
    const int wn   = warp & 3;            // 0..3
    const int q    = lane >> 2;           // 0..7
    const int t4   = lane & 3;            // 0..3

    const int n0  = blockIdx.x * 128;
    const int m0  = blockIdx.y * 128;
    const int seg = n0 >> 8;
    const int ncol = n0 & 255;

    const float* W    = (seg == 0) ? Wa : (seg == 1) ? Wb : (seg == 2) ? Wc : Wd;
    const float* bias = (seg == 0) ? ba : (seg == 1) ? bb : (seg == 2) ? bc : bd;
    const float* Ap   = (MODE == 2) ? g_rp : (MODE == 4) ? g_x : A;

    float acc[4][4][4];
    #pragma unroll
    for (int i = 0; i < 4; i++)
        #pragma unroll
        for (int j = 0; j < 4; j++)
            #pragma unroll
            for (int v = 0; v < 4; v++) acc[i][j][v] = 0.f;

    auto load_chunk = [&](int bi, int k0) {
        float* Asd = sm3 + bi * BUF_ELEMS;
        float* Bsd = Asd + AS_ELEMS;
        #pragma unroll
        for (int i = 0; i < 4; i++) {
            int g = i * 256 + tid;
            int m = g >> 3, c4 = (g & 7) << 2;
            cp_async16(smem_u32(&Asd[m * AS_STRIDE + c4]),
                       Ap + (size_t)(m0 + m) * LDA + k0 + c4);
        }
        #pragma unroll
        for (int i = 0; i < 4; i++) {
            int g = i * 256 + tid;
            int k = g >> 5, n4 = (g & 31) << 2;
            cp_async16(smem_u32(&Bsd[k * BS_STRIDE + n4]),
                       W + (size_t)(k0 + k) * 256 + ncol + n4);
        }
        cp_commit();
    };

    load_chunk(0, 0);
    load_chunk(1, 32);

    #pragma unroll
    for (int c = 0; c < KCH; c++) {
        if (c < KCH - 1) cp_wait<1>(); else cp_wait<0>();
        __syncthreads();
        // Buffer (c+2)%3 was consumed at iter c-1; barrier above makes reuse safe.
        if (c + 2 < KCH) load_chunk((c + 2) % 3, (c + 2) * 32);

        const float* Asb = sm3 + (c % 3) * BUF_ELEMS;
        const float* Bsb = Asb + AS_ELEMS;
        #pragma unroll
        for (int kk = 0; kk < 4; kk++) {
            uint32_t a[4][4], b[4][2];
            const int col = kk * 8 + t4;
            #pragma unroll
            for (int mt = 0; mt < 4; mt++) {
                const int r0 = wm * 64 + mt * 16 + q;
                a[mt][0] = __float_as_uint(Asb[r0 * AS_STRIDE + col]);
                a[mt][1] = __float_as_uint(Asb[(r0 + 8) * AS_STRIDE + col]);
                a[mt][2] = __float_as_uint(Asb[r0 * AS_STRIDE + col + 4]);
                a[mt][3] = __float_as_uint(Asb[(r0 + 8) * AS_STRIDE + col + 4]);
            }
            #pragma unroll
            for (int nt = 0; nt < 4; nt++) {
                const int nb = wn * 32 + nt * 8 + q;
                b[nt][0] = __float_as_uint(Bsb[col * BS_STRIDE + nb]);
                b[nt][1] = __float_as_uint(Bsb[(col + 4) * BS_STRIDE + nb]);
            }
            #pragma unroll
            for (int mt = 0; mt < 4; mt++)
                #pragma unroll
                for (int nt = 0; nt < 4; nt++)
                    mma_tf32(acc[mt][nt], a[mt], b[nt]);
        }
    }

    // ---------------- epilogue ----------------
    if (MODE == 3) {
        // Each warp covers 32 cols = exactly one head: head = n0/32 + wn.
        const int head = (n0 >> 5) + wn;
        #pragma unroll
        for (int mt = 0; mt < 4; mt++) {
            #pragma unroll
            for (int half = 0; half < 2; half++) {
                const int row = m0 + wm * 64 + mt * 16 + q + half * 8;
                const int b = row / 10, m = row - b * 10;
                const float* qp = g_curx + (size_t)b * 1024 + 768;
                float s = 0.f;
                #pragma unroll
                for (int nt = 0; nt < 4; nt++) {
                    const int col = n0 + wn * 32 + nt * 8 + 2 * t4;
                    float2 bk2 = *(const float2*)(ba + col);
                    float2 qv  = *(const float2*)(qp + col);
                    s += (acc[mt][nt][half * 2 + 0] + bk2.x) * qv.x
                       + (acc[mt][nt][half * 2 + 1] + bk2.y) * qv.y;
                }
                s += __shfl_xor_sync(0xffffffffu, s, 1);
                s += __shfl_xor_sync(0xffffffffu, s, 2);
                if (t4 == 0)
                    g_scores[((size_t)b * 8 + head) * 10 + m] = s;
            }
        }
        return;
    }

    #pragma unroll
    for (int mt = 0; mt < 4; mt++) {
        #pragma unroll
        for (int nt = 0; nt < 4; nt++) {
            const int hl = wn * 32 + nt * 8 + 2 * t4;
            const int h  = ncol + hl;
            #pragma unroll
            for (int half = 0; half < 2; half++) {
                const int row = m0 + wm * 64 + mt * 16 + q + half * 8;
                const float v0 = acc[mt][nt][half * 2 + 0];
                const float v1 = acc[mt][nt][half * 2 + 1];
                if (MODE == 0) {
                    float2 bb2 = *(const float2*)(bias + h);
                    float2 o = make_float2(v0 + bb2.x, v1 + bb2.y);
                    *(float2*)(g_curx + (size_t)row * 1024 + seg * 256 + h) = o;
                } else if (MODE == 1) {
                    const int b = row / 10;
                    if (seg == 0) {
                        float2 cx = *(const float2*)(g_curx + (size_t)b * 1024 + h);
                        float2 o = make_float2(sigmoidf_(v0 + cx.x), sigmoidf_(v1 + cx.y));
                        *(float2*)(g_z + (size_t)row * 256 + h) = o;
                    } else {
                        float2 cx = *(const float2*)(g_curx + (size_t)b * 1024 + 256 + h);
                        float2 pv = *(const float2*)(prev + (size_t)row * 256 + h);
                        float2 o = make_float2(sigmoidf_(v0 + cx.x) * pv.x,
                                               sigmoidf_(v1 + cx.y) * pv.y);
                        *(float2*)(g_rp + (size_t)row * 256 + h) = o;
                    }
                } else if (MODE == 2) {
                    const int b = row / 10;
                    float2 cx = *(const float2*)(g_curx + (size_t)b * 1024 + 512 + h);
                    float2 zz = *(const float2*)(g_z + (size_t)row * 256 + h);
                    float2 pv = *(const float2*)(prev + (size_t)row * 256 + h);
                    float c0 = tanhf(v0 + cx.x), c1 = tanhf(v1 + cx.y);
                    float2 o = make_float2((1.f - zz.x) * pv.x + zz.x * c0,
                                           (1.f - zz.y) * pv.y + zz.y * c1);
                    *(float2*)(out + (size_t)row * 256 + h) = o;
                } else {  // MODE 4: out projection -> g_f
                    float2 bb2 = *(const float2*)(bias + h);
                    float2 o = make_float2(v0 + bb2.x, v1 + bb2.y);
                    *(float2*)(g_f + (size_t)row * 256 + h) = o;
                }
            }
        }
    }
}

// ---------------------------------------------------------------------------
// attn_light: softmax + head-mean over g_scores, weighted memory, build x.
// GB=32 batches/CTA. Memory-bound.
// ---------------------------------------------------------------------------
#define GB_ 32

__global__ __launch_bounds__(256)
void attn_light(const float* __restrict__ cur,
                float* __restrict__ d_out)
{
    __shared__ float ss[GB_ * 80];
    __shared__ float sattn[GB_ * 10];

    const int tid = threadIdx.x;
    const int b0 = blockIdx.x * GB_;
    const float* upd = d_out + (size_t)B_ * 256;
    float* attn_out  = d_out + (size_t)B_ * 256 + (size_t)BM_ * 256;

    // load scores (apply 1/sqrt(32) here)
    const float scale = 0.17677669529663687f;
    for (int t = tid; t < GB_ * 80; t += 256)
        ss[t] = g_scores[(size_t)b0 * 80 + t] * scale;
    __syncthreads();

    // softmax over m per (bi, head)
    for (int t = tid; t < GB_ * 8; t += 256) {
        float* row = ss + t * 10;
        float mx = row[0];
        #pragma unroll
        for (int m = 1; m < 10; m++) mx = fmaxf(mx, row[m]);
        float e[10], sum = 0.f;
        #pragma unroll
        for (int m = 0; m < 10; m++) { e[m] = expf(row[m] - mx); sum += e[m]; }
        float inv = 1.f / sum;
        #pragma unroll
        for (int m = 0; m < 10; m++) row[m] = e[m] * inv;
    }
    __syncthreads();

    // head mean
    for (int t = tid; t < GB_ * 10; t += 256) {
        int bi = t / 10, m = t % 10;
        float s = 0.f;
        #pragma unroll
        for (int n = 0; n < 8; n++) s += ss[(bi * 8 + n) * 10 + m];
        s *= 0.125f;
        sattn[t] = s;
        attn_out[(size_t)(b0 + bi) * 10 + m] = s;
    }
    __syncthreads();

    // weighted memory; write x = [cur | weighted] to g_x
    for (int idx = tid; idx < GB_ * 256; idx += 256) {
        int bi = idx >> 8, h = idx & 255;
        size_t base = ((size_t)(b0 + bi) * 10) * 256 + h;
        float s = 0.f;
        #pragma unroll
        for (int m = 0; m < 10; m++) s += upd[base + m * 256] * sattn[bi * 10 + m];
        g_x[(size_t)(b0 + bi) * 512 + h]       = cur[(size_t)(b0 + bi) * 256 + h];
        g_x[(size_t)(b0 + bi) * 512 + 256 + h] = s;
    }
}

// ---------------------------------------------------------------------------
// LayerNorm over g_f -> d_out. One warp per row, 8 rows/CTA.
// ---------------------------------------------------------------------------
__global__ __launch_bounds__(256)
void ln_kernel(const float* __restrict__ gamma, const float* __restrict__ beta,
               float* __restrict__ d_out)
{
    const int warp = threadIdx.x >> 5;
    const int lane = threadIdx.x & 31;
    const int row  = blockIdx.x * 8 + warp;

    float v[8], sum = 0.f;
    const float* src = g_f + (size_t)row * 256;
    #pragma unroll
    for (int i = 0; i < 8; i++) { v[i] = src[lane + 32 * i]; sum += v[i]; }
    #pragma unroll
    for (int o = 16; o > 0; o >>= 1) sum += __shfl_xor_sync(0xffffffffu, sum, o);
    float mu = sum * (1.f / 256.f);
    float sq = 0.f;
    #pragma unroll
    for (int i = 0; i < 8; i++) { float d = v[i] - mu; sq += d * d; }
    #pragma unroll
    for (int o = 16; o > 0; o >>= 1) sq += __shfl_xor_sync(0xffffffffu, sq, o);
    float rstd = rsqrtf(sq * (1.f / 256.f) + 1e-5f);
    float* dst = d_out + (size_t)row * 256;
    #pragma unroll
    for (int i = 0; i < 8; i++) {
        int d_ = lane + 32 * i;
        dst[d_] = (v[i] - mu) * rstd * gamma[d_] + beta[d_];
    }
}

extern "C" void kernel_launch(void* const* d_in, const int* in_sizes, int n_in,
                              void* d_out, int out_size)
{
    (void)in_sizes; (void)n_in; (void)out_size;
    const float* cur    = (const float*)d_in[0];
    const float* prev   = (const float*)d_in[1];
    const float* Wz     = (const float*)d_in[2];
    const float* bz     = (const float*)d_in[3];
    const float* Wr     = (const float*)d_in[4];
    const float* br     = (const float*)d_in[5];
    const float* Wh     = (const float*)d_in[6];
    const float* bh     = (const float*)d_in[7];
    const float* Wq     = (const float*)d_in[8];
    const float* bq     = (const float*)d_in[9];
    const float* Wk     = (const float*)d_in[10];
    const float* bk     = (const float*)d_in[11];
    const float* Wo     = (const float*)d_in[12];
    const float* bo     = (const float*)d_in[13];
    const float* gamma2 = (const float*)d_in[14];
    const float* beta2  = (const float*)d_in[15];
    float* out = (float*)d_out;
    float* upd = out + (size_t)B_ * 256;

    cudaFuncSetAttribute(mma_gemm<0>, cudaFuncAttributeMaxDynamicSharedMemorySize, (int)GEMM_SMEM);
    cudaFuncSetAttribute(mma_gemm<1>, cudaFuncAttributeMaxDynamicSharedMemorySize, (int)GEMM_SMEM);
    cudaFuncSetAttribute(mma_gemm<2>, cudaFuncAttributeMaxDynamicSharedMemorySize, (int)GEMM_SMEM);
    cudaFuncSetAttribute(mma_gemm<3>, cudaFuncAttributeMaxDynamicSharedMemorySize, (int)GEMM_SMEM);
    cudaFuncSetAttribute(mma_gemm<4>, cudaFuncAttributeMaxDynamicSharedMemorySize, (int)GEMM_SMEM);

    dim3 blk(256);
    // 1) cur projections: [B,256] @ [256,1024]
    mma_gemm<0><<<dim3(8, B_ / 128), blk, GEMM_SMEM>>>(cur, Wz, Wr, Wh, Wq,
                                                       bz, br, bh, bq, nullptr, nullptr);
    // 2) z/r gates: [BM,256] @ [256,512]
    mma_gemm<1><<<dim3(4, BM_ / 128), blk, GEMM_SMEM>>>(prev, Wz + 65536, Wr + 65536, nullptr, nullptr,
                                                        nullptr, nullptr, nullptr, nullptr, prev, nullptr);
    // 3) cand + GRU update -> updated_memory
    mma_gemm<2><<<dim3(2, BM_ / 128), blk, GEMM_SMEM>>>(nullptr, Wh + 65536, nullptr, nullptr, nullptr,
                                                        nullptr, nullptr, nullptr, nullptr, prev, upd);
    // 4) k projection + fused attention scores -> g_scores
    mma_gemm<3><<<dim3(2, BM_ / 128), blk, GEMM_SMEM>>>(upd, Wk, nullptr, nullptr, nullptr,
                                                        bk, nullptr, nullptr, nullptr, nullptr, nullptr);
    // 5) softmax/head-mean/weighted -> g_x, attn weights
    attn_light<<<dim3(B_ / GB_), dim3(256)>>>(cur, out);
    // 6) output projection: [B,512] @ [512,256] -> g_f
    mma_gemm<4><<<dim3(2, B_ / 128), blk, GEMM_SMEM>>>(nullptr, Wo, nullptr, nullptr, nullptr,
                                                       bo, nullptr, nullptr, nullptr, nullptr, nullptr);
    // 7) LayerNorm -> d_out
    ln_kernel<<<dim3(B_ / 8), dim3(256)>>>(gamma2, beta2, out);
}